// round 12
// baseline (speedup 1.0000x reference)
#include <cuda_runtime.h>
#include <cuda_bf16.h>
#include <math.h>
#include <stdint.h>

// ---------------------------------------------------------------------------
// Problem constants
// ---------------------------------------------------------------------------
#define BB   2
#define LQ   12240
#define DMO  256
#define MH   8
#define ROWS (BB * LQ)     // 24480

__device__ __constant__ int c_H[4]  = {96, 48, 24, 12};
__device__ __constant__ int c_W[4]  = {96, 48, 24, 12};
__device__ __constant__ int c_ST[4] = {0, 9216, 11520, 12096};

// ---------------------------------------------------------------------------
// Scratch (static device globals: allocation-free, graph-safe)
// ---------------------------------------------------------------------------
__device__ float g_value[ROWS * DMO];
__device__ float g_offs [ROWS * DMO];
__device__ float g_alog [ROWS * 128];

// pre-split bf16 fragment-layout buffers (uint4 slots)
__device__ uint4 g_inpf_sp [ROWS * 64];
__device__ uint4 g_query_sp[ROWS * 64];
__device__ uint4 g_msout_sp[ROWS * 64];
__device__ uint4 g_Wv_sp[64 * 256];
__device__ uint4 g_Ws_sp[64 * 256];
__device__ uint4 g_Wa_sp[64 * 128];
__device__ uint4 g_Wo_sp[64 * 256];

// ---------------------------------------------------------------------------
// bf16 split: hi = truncate-to-bf16 (exact residual), lo = rn(a-hi).
// Slot = {P0h, P0l, P1h, P1l}; P0 = k{2t,2t+1}, P1 = k{8+2t,8+2t+1},
// packed bf16x2 with even-k element in the LOW half.
// ---------------------------------------------------------------------------
__device__ __forceinline__ uint4 split_pack(float2 p0, float2 p1) {
    uint32_t h0 = __float_as_uint(p0.x) & 0xFFFF0000u;
    uint32_t h1 = __float_as_uint(p0.y) & 0xFFFF0000u;
    uint32_t h2 = __float_as_uint(p1.x) & 0xFFFF0000u;
    uint32_t h3 = __float_as_uint(p1.y) & 0xFFFF0000u;
    float l0 = p0.x - __uint_as_float(h0);
    float l1 = p0.y - __uint_as_float(h1);
    float l2 = p1.x - __uint_as_float(h2);
    float l3 = p1.y - __uint_as_float(h3);
    uint4 r;
    r.x = __byte_perm(h0, h1, 0x7632);
    asm("cvt.rn.bf16x2.f32 %0, %1, %2;" : "=r"(r.y) : "f"(l1), "f"(l0));
    r.z = __byte_perm(h2, h3, 0x7632);
    asm("cvt.rn.bf16x2.f32 %0, %1, %2;" : "=r"(r.w) : "f"(l3), "f"(l2));
    return r;
}

__device__ __forceinline__ void mma_bf16(float4& c,
                                         uint32_t a0, uint32_t a1, uint32_t a2, uint32_t a3,
                                         uint32_t b0, uint32_t b1) {
    asm volatile(
        "mma.sync.aligned.m16n8k16.row.col.f32.bf16.bf16.f32 "
        "{%0,%1,%2,%3}, {%4,%5,%6,%7}, {%8,%9}, {%0,%1,%2,%3};"
        : "+f"(c.x), "+f"(c.y), "+f"(c.z), "+f"(c.w)
        : "r"(a0), "r"(a1), "r"(a2), "r"(a3), "r"(b0), "r"(b1));
}

__device__ __forceinline__ uint32_t smem_u32(const void* p) {
    uint32_t a;
    asm("{ .reg .u64 t; cvta.to.shared.u64 t, %1; cvt.u32.u64 %0, t; }"
        : "=r"(a) : "l"(p));
    return a;
}

__device__ __forceinline__ void cp16(uint32_t smem, const void* gmem, uint32_t sz) {
    asm volatile("cp.async.cg.shared.global [%0], [%1], 16, %2;"
                 :: "r"(smem), "l"(gmem), "r"(sz) : "memory");
}
#define CP_COMMIT() asm volatile("cp.async.commit_group;" ::: "memory")
#define CP_WAIT(n)  asm volatile("cp.async.wait_group %0;" :: "n"(n) : "memory")

// ---------------------------------------------------------------------------
// Pre-convert A-style matrices [rows x 256] f32 -> fragment-layout uint4.
// ---------------------------------------------------------------------------
__global__ void __launch_bounds__(256)
convert_A2(const float* __restrict__ A0, uint4* __restrict__ D0,
           const float* __restrict__ A1, uint4* __restrict__ D1, int rows)
{
    const float* src = blockIdx.y ? A1 : A0;
    uint4*       dst = blockIdx.y ? D1 : D0;
    int g = blockIdx.x * 256 + threadIdx.x;
    if (g >= rows * 64) return;
    int row  = g >> 6;
    int rest = g & 63;
    int chunk = rest >> 3;
    int s = (rest >> 2) & 1;
    int t = rest & 3;
    const float* p = src + (size_t)row * 256 + chunk * 32 + s * 16 + 2 * t;
    float2 p0 = *(const float2*)p;
    float2 p1 = *(const float2*)(p + 8);
    dst[g] = split_pack(p0, p1);
}

// ---------------------------------------------------------------------------
// Pre-convert weights [256 x ncols] f32 -> B fragment layout.
// ---------------------------------------------------------------------------
__global__ void __launch_bounds__(256)
convert_W4(const float* __restrict__ W0, uint4* __restrict__ D0, int n0,
           const float* __restrict__ W1, uint4* __restrict__ D1, int n1,
           const float* __restrict__ W2, uint4* __restrict__ D2, int n2,
           const float* __restrict__ W3, uint4* __restrict__ D3, int n3)
{
    const float* Wm; uint4* D; int ncols;
    switch (blockIdx.y) {
        case 0:  Wm = W0; D = D0; ncols = n0; break;
        case 1:  Wm = W1; D = D1; ncols = n1; break;
        case 2:  Wm = W2; D = D2; ncols = n2; break;
        default: Wm = W3; D = D3; ncols = n3; break;
    }
    int g = blockIdx.x * 256 + threadIdx.x;
    if (g >= 64 * ncols) return;
    int n    = g % ncols;
    int rest = g / ncols;
    int chunk = rest >> 3;
    int s = (rest >> 2) & 1;
    int t = rest & 3;
    int k = chunk * 32 + s * 16 + 2 * t;
    const float* p = Wm + (size_t)k * ncols + n;
    float2 p0 = make_float2(p[0], p[ncols]);
    float2 p1 = make_float2(p[8 * ncols], p[9 * ncols]);
    D[(size_t)(chunk * ncols + n) * 8 + s * 4 + t] = split_pack(p0, p1);
}

// ---------------------------------------------------------------------------
// Pre-split bf16 3-term GEMM + bias (unchanged from R11).
// ---------------------------------------------------------------------------
#define STAGE_U4   2304            // 1536 (A) + 768 (B)
#define GEMM_SMEM  (2 * STAGE_U4 * 16)   // 73728 B

__global__ void __launch_bounds__(256, 3)
gemm_split(const uint4* __restrict__ A0, const uint4* __restrict__ P0,
           const float* __restrict__ b0, float* __restrict__ C0, int nc0, int yt0,
           const uint4* __restrict__ A1, const uint4* __restrict__ P1,
           const float* __restrict__ b1, float* __restrict__ C1, int nc1, int yt1,
           const uint4* __restrict__ A2, const uint4* __restrict__ P2,
           const float* __restrict__ b2, float* __restrict__ C2, int nc2,
           int rows)
{
    extern __shared__ uint4 sm[];

    const int y = blockIdx.y;
    const uint4 *Asp, *Wsp;  const float* bias;  float* C;  int ncols, colBase;
    if (y < yt0) {
        Asp = A0; Wsp = P0; bias = b0; C = C0; ncols = nc0; colBase = y * 64;
    } else if (y < yt0 + yt1) {
        Asp = A1; Wsp = P1; bias = b1; C = C1; ncols = nc1; colBase = (y - yt0) * 64;
    } else {
        Asp = A2; Wsp = P2; bias = b2; C = C2; ncols = nc2; colBase = (y - yt0 - yt1) * 64;
    }

    const int tid  = threadIdx.x;
    const int lane = tid & 31;
    const int wid  = tid >> 5;
    const int wm   = wid & 3;
    const int wn   = wid >> 2;
    const int r    = lane >> 2;
    const int tig  = lane & 3;
    const int rowBase = blockIdx.x * 128;

    const uint32_t smem_base = smem_u32(sm);
    const int a_row  = tid >> 3;
    const int a_slot = tid & 7;

    float4 acc[2][4];
    #pragma unroll
    for (int mt = 0; mt < 2; mt++)
        #pragma unroll
        for (int nt = 0; nt < 4; nt++)
            acc[mt][nt] = make_float4(0.f, 0.f, 0.f, 0.f);

#define LOAD_CHUNK(KB, ST)                                                    \
    do {                                                                      \
        const uint32_t _base = smem_base + (ST) * (STAGE_U4 * 16);            \
        _Pragma("unroll")                                                     \
        for (int it = 0; it < 4; it++) {                                      \
            int row  = a_row + it * 32;                                       \
            int grow = rowBase + row;                                         \
            cp16(_base + (uint32_t)(row * 12 + a_slot) * 16,                  \
                 Asp + ((size_t)grow * 64 + (KB) * 8 + a_slot),               \
                 (grow < rows) ? 16u : 0u);                                   \
        }                                                                     \
        _Pragma("unroll")                                                     \
        for (int it = 0; it < 2; it++) {                                      \
            int n = a_row + it * 32;                                          \
            if (n < 64)                                                       \
                cp16(_base + (uint32_t)(1536 + n * 12 + a_slot) * 16,         \
                     Wsp + ((size_t)((KB) * ncols + colBase + n) * 8 + a_slot), 16u); \
        }                                                                     \
        CP_COMMIT();                                                          \
    } while (0)

    LOAD_CHUNK(0, 0);

    for (int kb = 0; kb < 8; kb++) {
        if (kb < 7) {
            LOAD_CHUNK(kb + 1, (kb + 1) & 1);
            CP_WAIT(1);
        } else {
            CP_WAIT(0);
        }
        __syncthreads();

        const uint4* As4 = sm + (kb & 1) * STAGE_U4;
        const uint4* Bs4 = As4 + 1536;

        #pragma unroll
        for (int s = 0; s < 2; s++) {
            uint4 aw[2][2];
            #pragma unroll
            for (int mt = 0; mt < 2; mt++) {
                const int ar = wm * 32 + mt * 16 + r;
                aw[mt][0] = As4[ar * 12 + s * 4 + tig];
                aw[mt][1] = As4[(ar + 8) * 12 + s * 4 + tig];
            }
            #pragma unroll
            for (int nt = 0; nt < 4; nt++) {
                uint4 bw = Bs4[(wn * 32 + nt * 8 + r) * 12 + s * 4 + tig];
                #pragma unroll
                for (int mt = 0; mt < 2; mt++) {
                    mma_bf16(acc[mt][nt], aw[mt][0].x, aw[mt][1].x, aw[mt][0].z, aw[mt][1].z, bw.x, bw.z);
                    mma_bf16(acc[mt][nt], aw[mt][0].y, aw[mt][1].y, aw[mt][0].w, aw[mt][1].w, bw.x, bw.z);
                    mma_bf16(acc[mt][nt], aw[mt][0].x, aw[mt][1].x, aw[mt][0].z, aw[mt][1].z, bw.y, bw.w);
                }
            }
        }
        __syncthreads();
    }
#undef LOAD_CHUNK

    #pragma unroll
    for (int nt = 0; nt < 4; nt++) {
        const int col = colBase + wn * 32 + nt * 8 + tig * 2;
        const float bb0 = bias[col], bb1 = bias[col + 1];
        #pragma unroll
        for (int mt = 0; mt < 2; mt++) {
            const int row0 = rowBase + wm * 32 + mt * 16 + r;
            const float4 c4 = acc[mt][nt];
            if (row0 < rows)
                *(float2*)(C + (size_t)row0 * ncols + col) =
                    make_float2(c4.x + bb0, c4.y + bb1);
            if (row0 + 8 < rows)
                *(float2*)(C + (size_t)(row0 + 8) * ncols + col) =
                    make_float2(c4.z + bb0, c4.w + bb1);
        }
    }
}

// ---------------------------------------------------------------------------
// Fused softmax + deformable bilinear sampling, v3.
// Changes vs R11:
//  - gather loop batches 2 points (8 LDG.128 in flight) before FMAs (MLP 4->8)
//  - epilogue emits the bf16-split fragment layout DIRECTLY (uint4 to
//    g_msout_sp via 8 shfl + split_pack), eliminating the separate convert
//    pass and the msout f32 round trip.
// ---------------------------------------------------------------------------
__global__ void __launch_bounds__(256)
sample_kernel(const float* __restrict__ value,
              const float* __restrict__ offs,
              const float* __restrict__ alog,
              const float* __restrict__ refp,
              uint4* __restrict__ msout_sp)
{
    __shared__ int4   sIdx[8][16];
    __shared__ float4 sWt [8][16];

    const int wid  = threadIdx.x >> 5;
    const int lane = threadIdx.x & 31;
    const int m    = wid;
    const int row  = blockIdx.x;
    const int b    = (row >= LQ) ? 1 : 0;

    // ---- softmax over 16 (l,p) logits via warp shuffles ----
    const float* lg = alog + (size_t)row * 128 + m * 16;
    float v = (lane < 16) ? lg[lane] : -1e30f;
    float mx = v;
    #pragma unroll
    for (int o = 16; o; o >>= 1) mx = fmaxf(mx, __shfl_xor_sync(0xffffffffu, mx, o));
    float e = (lane < 16) ? expf(v - mx) : 0.f;
    float s = e;
    #pragma unroll
    for (int o = 16; o; o >>= 1) s += __shfl_xor_sync(0xffffffffu, s, o);
    const float inv = 1.f / s;

    // ---- per-point setup ----
    if (lane < 16) {
        const int l  = lane >> 2;
        const int H  = c_H[l];
        const int W  = c_W[l];
        const int st = c_ST[l];
        const float fW = (float)W, fH = (float)H;

        const float rx = refp[(row * 4 + l) * 2 + 0];
        const float ry = refp[(row * 4 + l) * 2 + 1];
        const float* od = offs + (size_t)row * 256 + m * 32 + lane * 2;
        const float ox = od[0], oy = od[1];

        const float x = fmaf(rx, fW, ox) - 0.5f;
        const float y = fmaf(ry, fH, oy) - 0.5f;

        const float x0f = floorf(x), y0f = floorf(y);
        const float fx = x - x0f, fy = y - y0f;
        const int ix = (int)x0f, iy = (int)y0f;

        const float lw = e * inv;
        float w00 = (1.f - fx) * (1.f - fy) * lw;
        float w01 = fx * (1.f - fy) * lw;
        float w10 = (1.f - fx) * fy * lw;
        float w11 = fx * fy * lw;

        const bool vx0 = (ix >= 0) && (ix < W);
        const bool vx1 = (ix + 1 >= 0) && (ix + 1 < W);
        const bool vy0 = (iy >= 0) && (iy < H);
        const bool vy1 = (iy + 1 >= 0) && (iy + 1 < H);
        if (!(vx0 && vy0)) w00 = 0.f;
        if (!(vx1 && vy0)) w01 = 0.f;
        if (!(vx0 && vy1)) w10 = 0.f;
        if (!(vx1 && vy1)) w11 = 0.f;

        const int cx0 = min(max(ix, 0), W - 1);
        const int cx1 = min(max(ix + 1, 0), W - 1);
        const int cy0 = min(max(iy, 0), H - 1);
        const int cy1 = min(max(iy + 1, 0), H - 1);
        const int r0 = st + cy0 * W;
        const int r1 = st + cy1 * W;

        sIdx[wid][lane] = make_int4((r0 + cx0) * 256, (r0 + cx1) * 256,
                                    (r1 + cx0) * 256, (r1 + cx1) * 256);
        sWt [wid][lane] = make_float4(w00, w01, w10, w11);
    }
    __syncwarp();

    // ---- gather: group g (8 lanes, float4 = 32 channels), 2 points/batch ----
    const int g  = lane >> 3;
    const int c4 = (lane & 7) * 4;
    const float* vb4 = value + (size_t)b * LQ * 256 + m * 32 + c4;

    float4 acc = make_float4(0.f, 0.f, 0.f, 0.f);
    #pragma unroll
    for (int h = 0; h < 2; h++) {
        const int pa = g * 4 + h * 2;
        const int4   Ia = sIdx[wid][pa];
        const int4   Ib = sIdx[wid][pa + 1];
        const float4 Wa_ = sWt[wid][pa];
        const float4 Wb_ = sWt[wid][pa + 1];
        // 8 independent 128B gathers in flight
        float4 a0 = *(const float4*)(vb4 + Ia.x);
        float4 a1 = *(const float4*)(vb4 + Ia.y);
        float4 a2 = *(const float4*)(vb4 + Ia.z);
        float4 a3 = *(const float4*)(vb4 + Ia.w);
        float4 b0 = *(const float4*)(vb4 + Ib.x);
        float4 b1 = *(const float4*)(vb4 + Ib.y);
        float4 b2 = *(const float4*)(vb4 + Ib.z);
        float4 b3 = *(const float4*)(vb4 + Ib.w);
        acc.x = fmaf(Wa_.x, a0.x, fmaf(Wa_.y, a1.x, fmaf(Wa_.z, a2.x, fmaf(Wa_.w, a3.x, acc.x))));
        acc.y = fmaf(Wa_.x, a0.y, fmaf(Wa_.y, a1.y, fmaf(Wa_.z, a2.y, fmaf(Wa_.w, a3.y, acc.y))));
        acc.z = fmaf(Wa_.x, a0.z, fmaf(Wa_.y, a1.z, fmaf(Wa_.z, a2.z, fmaf(Wa_.w, a3.z, acc.z))));
        acc.w = fmaf(Wa_.x, a0.w, fmaf(Wa_.y, a1.w, fmaf(Wa_.z, a2.w, fmaf(Wa_.w, a3.w, acc.w))));
        acc.x = fmaf(Wb_.x, b0.x, fmaf(Wb_.y, b1.x, fmaf(Wb_.z, b2.x, fmaf(Wb_.w, b3.x, acc.x))));
        acc.y = fmaf(Wb_.x, b0.y, fmaf(Wb_.y, b1.y, fmaf(Wb_.z, b2.y, fmaf(Wb_.w, b3.y, acc.y))));
        acc.z = fmaf(Wb_.x, b0.z, fmaf(Wb_.y, b1.z, fmaf(Wb_.z, b2.z, fmaf(Wb_.w, b3.z, acc.z))));
        acc.w = fmaf(Wb_.x, b0.w, fmaf(Wb_.y, b1.w, fmaf(Wb_.z, b2.w, fmaf(Wb_.w, b3.w, acc.w))));
    }

    // ---- butterfly over the 4 groups: all lanes end with full channel sums ----
    #pragma unroll
    for (int o = 8; o <= 16; o <<= 1) {
        acc.x += __shfl_xor_sync(0xffffffffu, acc.x, o);
        acc.y += __shfl_xor_sync(0xffffffffu, acc.y, o);
        acc.z += __shfl_xor_sync(0xffffffffu, acc.z, o);
        acc.w += __shfl_xor_sync(0xffffffffu, acc.w, o);
    }

    // ---- fused epilogue: emit bf16-split fragment slot directly ----
    // Slot j = s*4+t covers k_local = s*16+2t; needs channel pairs
    // {k, k+1} (lane 4s + (t>>1)) and {k+8, k+9} (lane 4s + 2 + (t>>1)),
    // components (x,y) for even t, (z,w) for odd t.
    {
        const int j  = lane & 7;
        const int sI = (j >> 2) & 1;
        const int tI = j & 3;
        const int src0 = 4 * sI + (tI >> 1);
        const int src1 = src0 + 2;

        float x0 = __shfl_sync(0xffffffffu, acc.x, src0);
        float y0 = __shfl_sync(0xffffffffu, acc.y, src0);
        float z0 = __shfl_sync(0xffffffffu, acc.z, src0);
        float w0 = __shfl_sync(0xffffffffu, acc.w, src0);
        float x1 = __shfl_sync(0xffffffffu, acc.x, src1);
        float y1 = __shfl_sync(0xffffffffu, acc.y, src1);
        float z1 = __shfl_sync(0xffffffffu, acc.z, src1);
        float w1 = __shfl_sync(0xffffffffu, acc.w, src1);

        const bool odd = (tI & 1);
        float2 p0 = odd ? make_float2(z0, w0) : make_float2(x0, y0);
        float2 p1 = odd ? make_float2(z1, w1) : make_float2(x1, y1);

        if (lane < 8)
            msout_sp[(size_t)row * 64 + m * 8 + j] = split_pack(p0, p1);
    }
}

// ---------------------------------------------------------------------------
// Launch: 5 graph-capturable kernel launches.
// ---------------------------------------------------------------------------
extern "C" void kernel_launch(void* const* d_in, const int* in_sizes, int n_in,
                              void* d_out, int out_size)
{
    (void)in_sizes; (void)n_in; (void)out_size;

    const float* query = (const float*)d_in[0];
    const float* refp  = (const float*)d_in[1];
    const float* inpf  = (const float*)d_in[2];
    const float* Wv = (const float*)d_in[4];
    const float* bv = (const float*)d_in[5];
    const float* Ws = (const float*)d_in[6];
    const float* bs = (const float*)d_in[7];
    const float* Wa = (const float*)d_in[8];
    const float* ba = (const float*)d_in[9];
    const float* Wo = (const float*)d_in[10];
    const float* bo = (const float*)d_in[11];
    float* out = (float*)d_out;

    float *value, *offs, *alog;
    uint4 *inpf_sp, *query_sp, *msout_sp, *Wv_sp, *Ws_sp, *Wa_sp, *Wo_sp;
    cudaGetSymbolAddress((void**)&value, g_value);
    cudaGetSymbolAddress((void**)&offs,  g_offs);
    cudaGetSymbolAddress((void**)&alog,  g_alog);
    cudaGetSymbolAddress((void**)&inpf_sp,  g_inpf_sp);
    cudaGetSymbolAddress((void**)&query_sp, g_query_sp);
    cudaGetSymbolAddress((void**)&msout_sp, g_msout_sp);
    cudaGetSymbolAddress((void**)&Wv_sp, g_Wv_sp);
    cudaGetSymbolAddress((void**)&Ws_sp, g_Ws_sp);
    cudaGetSymbolAddress((void**)&Wa_sp, g_Wa_sp);
    cudaGetSymbolAddress((void**)&Wo_sp, g_Wo_sp);

    cudaFuncSetAttribute(gemm_split, cudaFuncAttributeMaxDynamicSharedMemorySize,
                         GEMM_SMEM);

    const dim3 blk(256);
    const int  mTiles = (ROWS + 127) / 128;        // 192
    const int  aBlocks = ROWS * 64 / 256;          // 6120

    // 1) weights -> split fragment layout (tiny)
    convert_W4<<<dim3(64, 4), blk>>>(Wv, Wv_sp, 256, Ws, Ws_sp, 256,
                                     Wa, Wa_sp, 128, Wo, Wo_sp, 256);
    // 2) inpf + query -> split fragment layout
    convert_A2<<<dim3(aBlocks, 2), blk>>>(inpf, inpf_sp, query, query_sp, ROWS);
    // 3) value / offs / alog in ONE launch (y = 4 + 4 + 2 = 10)
    gemm_split<<<dim3(mTiles, 10), blk, GEMM_SMEM>>>(
        inpf_sp,  Wv_sp, bv, value, 256, 4,
        query_sp, Ws_sp, bs, offs,  256, 4,
        query_sp, Wa_sp, ba, alog,  128,
        ROWS);
    // 4) fused softmax + sampling + bf16-split epilogue (writes msout_sp)
    sample_kernel<<<ROWS, blk>>>(value, offs, alog, refp, msout_sp);
    // 5) out = msout @ Wo + bo
    gemm_split<<<dim3(mTiles, 4), blk, GEMM_SMEM>>>(
        msout_sp, Wo_sp, bo, out, 256, 4,
        msout_sp, Wo_sp, bo, out, 256, 0,
        msout_sp, Wo_sp, bo, out, 256,
        ROWS);
}

// round 13
// speedup vs baseline: 1.0103x; 1.0103x over previous
#include <cuda_runtime.h>
#include <cuda_bf16.h>
#include <math.h>
#include <stdint.h>

// ---------------------------------------------------------------------------
// Problem constants
// ---------------------------------------------------------------------------
#define BB   2
#define LQ   12240
#define DMO  256
#define MH   8
#define ROWS (BB * LQ)     // 24480

__device__ __constant__ int c_H[4]  = {96, 48, 24, 12};
__device__ __constant__ int c_W[4]  = {96, 48, 24, 12};
__device__ __constant__ int c_ST[4] = {0, 9216, 11520, 12096};

// ---------------------------------------------------------------------------
// Scratch (static device globals: allocation-free, graph-safe)
// ---------------------------------------------------------------------------
__device__ float g_value[ROWS * DMO];
__device__ float g_offs [ROWS * DMO];
__device__ float g_alog [ROWS * 128];

// pre-split bf16 fragment-layout buffers (uint4 slots)
__device__ uint4 g_inpf_sp [ROWS * 64];
__device__ uint4 g_query_sp[ROWS * 64];
__device__ uint4 g_msout_sp[ROWS * 64];
__device__ uint4 g_Wv_sp[64 * 256];
__device__ uint4 g_Ws_sp[64 * 256];
__device__ uint4 g_Wa_sp[64 * 128];
__device__ uint4 g_Wo_sp[64 * 256];

// ---------------------------------------------------------------------------
// bf16 split: hi = truncate-to-bf16 (exact residual), lo = rn(a-hi).
// ---------------------------------------------------------------------------
__device__ __forceinline__ uint4 split_pack(float2 p0, float2 p1) {
    uint32_t h0 = __float_as_uint(p0.x) & 0xFFFF0000u;
    uint32_t h1 = __float_as_uint(p0.y) & 0xFFFF0000u;
    uint32_t h2 = __float_as_uint(p1.x) & 0xFFFF0000u;
    uint32_t h3 = __float_as_uint(p1.y) & 0xFFFF0000u;
    float l0 = p0.x - __uint_as_float(h0);
    float l1 = p0.y - __uint_as_float(h1);
    float l2 = p1.x - __uint_as_float(h2);
    float l3 = p1.y - __uint_as_float(h3);
    uint4 r;
    r.x = __byte_perm(h0, h1, 0x7632);
    asm("cvt.rn.bf16x2.f32 %0, %1, %2;" : "=r"(r.y) : "f"(l1), "f"(l0));
    r.z = __byte_perm(h2, h3, 0x7632);
    asm("cvt.rn.bf16x2.f32 %0, %1, %2;" : "=r"(r.w) : "f"(l3), "f"(l2));
    return r;
}

__device__ __forceinline__ void mma_bf16(float4& c,
                                         uint32_t a0, uint32_t a1, uint32_t a2, uint32_t a3,
                                         uint32_t b0, uint32_t b1) {
    asm volatile(
        "mma.sync.aligned.m16n8k16.row.col.f32.bf16.bf16.f32 "
        "{%0,%1,%2,%3}, {%4,%5,%6,%7}, {%8,%9}, {%0,%1,%2,%3};"
        : "+f"(c.x), "+f"(c.y), "+f"(c.z), "+f"(c.w)
        : "r"(a0), "r"(a1), "r"(a2), "r"(a3), "r"(b0), "r"(b1));
}

__device__ __forceinline__ uint32_t smem_u32(const void* p) {
    uint32_t a;
    asm("{ .reg .u64 t; cvta.to.shared.u64 t, %1; cvt.u32.u64 %0, t; }"
        : "=r"(a) : "l"(p));
    return a;
}

__device__ __forceinline__ void cp16(uint32_t smem, const void* gmem, uint32_t sz) {
    asm volatile("cp.async.cg.shared.global [%0], [%1], 16, %2;"
                 :: "r"(smem), "l"(gmem), "r"(sz) : "memory");
}
#define CP_COMMIT() asm volatile("cp.async.commit_group;" ::: "memory")
#define CP_WAIT(n)  asm volatile("cp.async.wait_group %0;" :: "n"(n) : "memory")

// Ordered (non-reorderable) read-only vector load — forces MLP.
#define LDG4_NC(dst, ptr)                                                     \
    asm volatile("ld.global.nc.v4.f32 {%0,%1,%2,%3}, [%4];"                   \
                 : "=f"((dst).x), "=f"((dst).y), "=f"((dst).z), "=f"((dst).w) \
                 : "l"(ptr))

// ---------------------------------------------------------------------------
// Pre-convert A-style matrices [rows x 256] f32 -> fragment-layout uint4.
// ---------------------------------------------------------------------------
__global__ void __launch_bounds__(256)
convert_A2(const float* __restrict__ A0, uint4* __restrict__ D0,
           const float* __restrict__ A1, uint4* __restrict__ D1, int rows)
{
    const float* src = blockIdx.y ? A1 : A0;
    uint4*       dst = blockIdx.y ? D1 : D0;
    int g = blockIdx.x * 256 + threadIdx.x;
    if (g >= rows * 64) return;
    int row  = g >> 6;
    int rest = g & 63;
    int chunk = rest >> 3;
    int s = (rest >> 2) & 1;
    int t = rest & 3;
    const float* p = src + (size_t)row * 256 + chunk * 32 + s * 16 + 2 * t;
    float2 p0 = *(const float2*)p;
    float2 p1 = *(const float2*)(p + 8);
    dst[g] = split_pack(p0, p1);
}

// ---------------------------------------------------------------------------
// Pre-convert weights [256 x ncols] f32 -> B fragment layout.
// ---------------------------------------------------------------------------
__global__ void __launch_bounds__(256)
convert_W4(const float* __restrict__ W0, uint4* __restrict__ D0, int n0,
           const float* __restrict__ W1, uint4* __restrict__ D1, int n1,
           const float* __restrict__ W2, uint4* __restrict__ D2, int n2,
           const float* __restrict__ W3, uint4* __restrict__ D3, int n3)
{
    const float* Wm; uint4* D; int ncols;
    switch (blockIdx.y) {
        case 0:  Wm = W0; D = D0; ncols = n0; break;
        case 1:  Wm = W1; D = D1; ncols = n1; break;
        case 2:  Wm = W2; D = D2; ncols = n2; break;
        default: Wm = W3; D = D3; ncols = n3; break;
    }
    int g = blockIdx.x * 256 + threadIdx.x;
    if (g >= 64 * ncols) return;
    int n    = g % ncols;
    int rest = g / ncols;
    int chunk = rest >> 3;
    int s = (rest >> 2) & 1;
    int t = rest & 3;
    int k = chunk * 32 + s * 16 + 2 * t;
    const float* p = Wm + (size_t)k * ncols + n;
    float2 p0 = make_float2(p[0], p[ncols]);
    float2 p1 = make_float2(p[8 * ncols], p[9 * ncols]);
    D[(size_t)(chunk * ncols + n) * 8 + s * 4 + t] = split_pack(p0, p1);
}

// ---------------------------------------------------------------------------
// Pre-split bf16 3-term GEMM + bias. Block tile 128x128 (BN widened from 64),
// 8 warps = 4(M) x 2(N), warp tile 32x64 (acc[2][8]). K chunk 32,
// double-buffered cp.async. ncols=128 handled as a single 128-wide tile.
// ---------------------------------------------------------------------------
#define STAGE_U4   3072            // 1536 (A: 128rows x 12) + 1536 (B: 128n x 12)
#define GEMM_SMEM  (2 * STAGE_U4 * 16)   // 98304 B

__global__ void __launch_bounds__(256)
gemm_split(const uint4* __restrict__ A0, const uint4* __restrict__ P0,
           const float* __restrict__ b0, float* __restrict__ C0, int nc0, int yt0,
           const uint4* __restrict__ A1, const uint4* __restrict__ P1,
           const float* __restrict__ b1, float* __restrict__ C1, int nc1, int yt1,
           const uint4* __restrict__ A2, const uint4* __restrict__ P2,
           const float* __restrict__ b2, float* __restrict__ C2, int nc2,
           int rows)
{
    extern __shared__ uint4 sm[];

    const int y = blockIdx.y;
    const uint4 *Asp, *Wsp;  const float* bias;  float* C;  int ncols, colBase;
    if (y < yt0) {
        Asp = A0; Wsp = P0; bias = b0; C = C0; ncols = nc0; colBase = y * 128;
    } else if (y < yt0 + yt1) {
        Asp = A1; Wsp = P1; bias = b1; C = C1; ncols = nc1; colBase = (y - yt0) * 128;
    } else {
        Asp = A2; Wsp = P2; bias = b2; C = C2; ncols = nc2; colBase = (y - yt0 - yt1) * 128;
    }

    const int tid  = threadIdx.x;
    const int lane = tid & 31;
    const int wid  = tid >> 5;
    const int wm   = wid & 3;          // rows wm*32
    const int wn   = wid >> 2;         // cols wn*64
    const int r    = lane >> 2;
    const int tig  = lane & 3;
    const int rowBase = blockIdx.x * 128;

    const uint32_t smem_base = smem_u32(sm);
    const int a_row  = tid >> 3;       // 0..31 (+32*it)
    const int a_slot = tid & 7;

    float4 acc[2][8];
    #pragma unroll
    for (int mt = 0; mt < 2; mt++)
        #pragma unroll
        for (int nt = 0; nt < 8; nt++)
            acc[mt][nt] = make_float4(0.f, 0.f, 0.f, 0.f);

#define LOAD_CHUNK(KB, ST)                                                    \
    do {                                                                      \
        const uint32_t _base = smem_base + (ST) * (STAGE_U4 * 16);            \
        _Pragma("unroll")                                                     \
        for (int it = 0; it < 4; it++) {                                      \
            int row  = a_row + it * 32;                                       \
            int grow = rowBase + row;                                         \
            cp16(_base + (uint32_t)(row * 12 + a_slot) * 16,                  \
                 Asp + ((size_t)grow * 64 + (KB) * 8 + a_slot),               \
                 (grow < rows) ? 16u : 0u);                                   \
        }                                                                     \
        _Pragma("unroll")                                                     \
        for (int it = 0; it < 4; it++) {                                      \
            int n = a_row + it * 32;   /* 0..127 */                           \
            cp16(_base + (uint32_t)(1536 + n * 12 + a_slot) * 16,             \
                 Wsp + ((size_t)((KB) * ncols + colBase + n) * 8 + a_slot), 16u); \
        }                                                                     \
        CP_COMMIT();                                                          \
    } while (0)

    LOAD_CHUNK(0, 0);

    for (int kb = 0; kb < 8; kb++) {
        if (kb < 7) {
            LOAD_CHUNK(kb + 1, (kb + 1) & 1);
            CP_WAIT(1);
        } else {
            CP_WAIT(0);
        }
        __syncthreads();

        const uint4* As4 = sm + (kb & 1) * STAGE_U4;
        const uint4* Bs4 = As4 + 1536;

        #pragma unroll
        for (int s = 0; s < 2; s++) {
            uint4 aw[2][2];
            #pragma unroll
            for (int mt = 0; mt < 2; mt++) {
                const int ar = wm * 32 + mt * 16 + r;
                aw[mt][0] = As4[ar * 12 + s * 4 + tig];
                aw[mt][1] = As4[(ar + 8) * 12 + s * 4 + tig];
            }
            #pragma unroll
            for (int nt = 0; nt < 8; nt++) {
                uint4 bw = Bs4[(wn * 64 + nt * 8 + r) * 12 + s * 4 + tig];
                #pragma unroll
                for (int mt = 0; mt < 2; mt++) {
                    mma_bf16(acc[mt][nt], aw[mt][0].x, aw[mt][1].x, aw[mt][0].z, aw[mt][1].z, bw.x, bw.z);
                    mma_bf16(acc[mt][nt], aw[mt][0].y, aw[mt][1].y, aw[mt][0].w, aw[mt][1].w, bw.x, bw.z);
                    mma_bf16(acc[mt][nt], aw[mt][0].x, aw[mt][1].x, aw[mt][0].z, aw[mt][1].z, bw.y, bw.w);
                }
            }
        }
        __syncthreads();
    }
#undef LOAD_CHUNK

    // ---- epilogue: +bias, float2 stores ----
    #pragma unroll
    for (int nt = 0; nt < 8; nt++) {
        const int col = colBase + wn * 64 + nt * 8 + tig * 2;
        const float bb0 = bias[col], bb1 = bias[col + 1];
        #pragma unroll
        for (int mt = 0; mt < 2; mt++) {
            const int row0 = rowBase + wm * 32 + mt * 16 + r;
            const float4 c4 = acc[mt][nt];
            if (row0 < rows)
                *(float2*)(C + (size_t)row0 * ncols + col) =
                    make_float2(c4.x + bb0, c4.y + bb1);
            if (row0 + 8 < rows)
                *(float2*)(C + (size_t)(row0 + 8) * ncols + col) =
                    make_float2(c4.z + bb0, c4.w + bb1);
        }
    }
}

// ---------------------------------------------------------------------------
// Fused softmax + deformable bilinear sampling, v4.
// Gather uses ORDERED asm ld.global.nc.v4 — 8 loads issued back-to-back
// before any FMA (forced MLP=8; ptxas cannot re-serialize volatile asm).
// Epilogue emits the bf16-split fragment layout directly.
// ---------------------------------------------------------------------------
__global__ void __launch_bounds__(256)
sample_kernel(const float* __restrict__ value,
              const float* __restrict__ offs,
              const float* __restrict__ alog,
              const float* __restrict__ refp,
              uint4* __restrict__ msout_sp)
{
    __shared__ int4   sIdx[8][16];
    __shared__ float4 sWt [8][16];

    const int wid  = threadIdx.x >> 5;
    const int lane = threadIdx.x & 31;
    const int m    = wid;
    const int row  = blockIdx.x;
    const int b    = (row >= LQ) ? 1 : 0;

    // ---- softmax over 16 (l,p) logits ----
    const float* lg = alog + (size_t)row * 128 + m * 16;
    float v = (lane < 16) ? lg[lane] : -1e30f;
    float mx = v;
    #pragma unroll
    for (int o = 16; o; o >>= 1) mx = fmaxf(mx, __shfl_xor_sync(0xffffffffu, mx, o));
    float e = (lane < 16) ? expf(v - mx) : 0.f;
    float s = e;
    #pragma unroll
    for (int o = 16; o; o >>= 1) s += __shfl_xor_sync(0xffffffffu, s, o);
    const float inv = 1.f / s;

    // ---- per-point setup ----
    if (lane < 16) {
        const int l  = lane >> 2;
        const int H  = c_H[l];
        const int W  = c_W[l];
        const int st = c_ST[l];
        const float fW = (float)W, fH = (float)H;

        const float rx = refp[(row * 4 + l) * 2 + 0];
        const float ry = refp[(row * 4 + l) * 2 + 1];
        const float* od = offs + (size_t)row * 256 + m * 32 + lane * 2;
        const float ox = od[0], oy = od[1];

        const float x = fmaf(rx, fW, ox) - 0.5f;
        const float y = fmaf(ry, fH, oy) - 0.5f;

        const float x0f = floorf(x), y0f = floorf(y);
        const float fx = x - x0f, fy = y - y0f;
        const int ix = (int)x0f, iy = (int)y0f;

        const float lw = e * inv;
        float w00 = (1.f - fx) * (1.f - fy) * lw;
        float w01 = fx * (1.f - fy) * lw;
        float w10 = (1.f - fx) * fy * lw;
        float w11 = fx * fy * lw;

        const bool vx0 = (ix >= 0) && (ix < W);
        const bool vx1 = (ix + 1 >= 0) && (ix + 1 < W);
        const bool vy0 = (iy >= 0) && (iy < H);
        const bool vy1 = (iy + 1 >= 0) && (iy + 1 < H);
        if (!(vx0 && vy0)) w00 = 0.f;
        if (!(vx1 && vy0)) w01 = 0.f;
        if (!(vx0 && vy1)) w10 = 0.f;
        if (!(vx1 && vy1)) w11 = 0.f;

        const int cx0 = min(max(ix, 0), W - 1);
        const int cx1 = min(max(ix + 1, 0), W - 1);
        const int cy0 = min(max(iy, 0), H - 1);
        const int cy1 = min(max(iy + 1, 0), H - 1);
        const int r0 = st + cy0 * W;
        const int r1 = st + cy1 * W;

        sIdx[wid][lane] = make_int4((r0 + cx0) * 256, (r0 + cx1) * 256,
                                    (r1 + cx0) * 256, (r1 + cx1) * 256);
        sWt [wid][lane] = make_float4(w00, w01, w10, w11);
    }
    __syncwarp();

    // ---- gather: group g (8 lanes, float4 = 32 channels), 2 points/batch,
    //      8 ordered LDG.128 in flight per batch ----
    const int g  = lane >> 3;
    const int c4 = (lane & 7) * 4;
    const float* vb4 = value + (size_t)b * LQ * 256 + m * 32 + c4;

    float4 acc = make_float4(0.f, 0.f, 0.f, 0.f);
    #pragma unroll
    for (int h = 0; h < 2; h++) {
        const int pa = g * 4 + h * 2;
        const int4   Ia = sIdx[wid][pa];
        const int4   Ib = sIdx[wid][pa + 1];
        const float4 Wa_ = sWt[wid][pa];
        const float4 Wb_ = sWt[wid][pa + 1];
        float4 a0, a1, a2, a3, b0, b1, b2, b3;
        LDG4_NC(a0, vb4 + Ia.x);
        LDG4_NC(a1, vb4 + Ia.y);
        LDG4_NC(a2, vb4 + Ia.z);
        LDG4_NC(a3, vb4 + Ia.w);
        LDG4_NC(b0, vb4 + Ib.x);
        LDG4_NC(b1, vb4 + Ib.y);
        LDG4_NC(b2, vb4 + Ib.z);
        LDG4_NC(b3, vb4 + Ib.w);
        acc.x = fmaf(Wa_.x, a0.x, fmaf(Wa_.y, a1.x, fmaf(Wa_.z, a2.x, fmaf(Wa_.w, a3.x, acc.x))));
        acc.y = fmaf(Wa_.x, a0.y, fmaf(Wa_.y, a1.y, fmaf(Wa_.z, a2.y, fmaf(Wa_.w, a3.y, acc.y))));
        acc.z = fmaf(Wa_.x, a0.z, fmaf(Wa_.y, a1.z, fmaf(Wa_.z, a2.z, fmaf(Wa_.w, a3.z, acc.z))));
        acc.w = fmaf(Wa_.x, a0.w, fmaf(Wa_.y, a1.w, fmaf(Wa_.z, a2.w, fmaf(Wa_.w, a3.w, acc.w))));
        acc.x = fmaf(Wb_.x, b0.x, fmaf(Wb_.y, b1.x, fmaf(Wb_.z, b2.x, fmaf(Wb_.w, b3.x, acc.x))));
        acc.y = fmaf(Wb_.x, b0.y, fmaf(Wb_.y, b1.y, fmaf(Wb_.z, b2.y, fmaf(Wb_.w, b3.y, acc.y))));
        acc.z = fmaf(Wb_.x, b0.z, fmaf(Wb_.y, b1.z, fmaf(Wb_.z, b2.z, fmaf(Wb_.w, b3.z, acc.z))));
        acc.w = fmaf(Wb_.x, b0.w, fmaf(Wb_.y, b1.w, fmaf(Wb_.z, b2.w, fmaf(Wb_.w, b3.w, acc.w))));
    }

    // ---- butterfly over the 4 groups ----
    #pragma unroll
    for (int o = 8; o <= 16; o <<= 1) {
        acc.x += __shfl_xor_sync(0xffffffffu, acc.x, o);
        acc.y += __shfl_xor_sync(0xffffffffu, acc.y, o);
        acc.z += __shfl_xor_sync(0xffffffffu, acc.z, o);
        acc.w += __shfl_xor_sync(0xffffffffu, acc.w, o);
    }

    // ---- fused epilogue: emit bf16-split fragment slot directly ----
    {
        const int j  = lane & 7;
        const int sI = (j >> 2) & 1;
        const int tI = j & 3;
        const int src0 = 4 * sI + (tI >> 1);
        const int src1 = src0 + 2;

        float x0 = __shfl_sync(0xffffffffu, acc.x, src0);
        float y0 = __shfl_sync(0xffffffffu, acc.y, src0);
        float z0 = __shfl_sync(0xffffffffu, acc.z, src0);
        float w0 = __shfl_sync(0xffffffffu, acc.w, src0);
        float x1 = __shfl_sync(0xffffffffu, acc.x, src1);
        float y1 = __shfl_sync(0xffffffffu, acc.y, src1);
        float z1 = __shfl_sync(0xffffffffu, acc.z, src1);
        float w1 = __shfl_sync(0xffffffffu, acc.w, src1);

        const bool odd = (tI & 1);
        float2 p0 = odd ? make_float2(z0, w0) : make_float2(x0, y0);
        float2 p1 = odd ? make_float2(z1, w1) : make_float2(x1, y1);

        if (lane < 8)
            msout_sp[(size_t)row * 64 + m * 8 + j] = split_pack(p0, p1);
    }
}

// ---------------------------------------------------------------------------
// Launch: 5 graph-capturable kernel launches.
// ---------------------------------------------------------------------------
extern "C" void kernel_launch(void* const* d_in, const int* in_sizes, int n_in,
                              void* d_out, int out_size)
{
    (void)in_sizes; (void)n_in; (void)out_size;

    const float* query = (const float*)d_in[0];
    const float* refp  = (const float*)d_in[1];
    const float* inpf  = (const float*)d_in[2];
    const float* Wv = (const float*)d_in[4];
    const float* bv = (const float*)d_in[5];
    const float* Ws = (const float*)d_in[6];
    const float* bs = (const float*)d_in[7];
    const float* Wa = (const float*)d_in[8];
    const float* ba = (const float*)d_in[9];
    const float* Wo = (const float*)d_in[10];
    const float* bo = (const float*)d_in[11];
    float* out = (float*)d_out;

    float *value, *offs, *alog;
    uint4 *inpf_sp, *query_sp, *msout_sp, *Wv_sp, *Ws_sp, *Wa_sp, *Wo_sp;
    cudaGetSymbolAddress((void**)&value, g_value);
    cudaGetSymbolAddress((void**)&offs,  g_offs);
    cudaGetSymbolAddress((void**)&alog,  g_alog);
    cudaGetSymbolAddress((void**)&inpf_sp,  g_inpf_sp);
    cudaGetSymbolAddress((void**)&query_sp, g_query_sp);
    cudaGetSymbolAddress((void**)&msout_sp, g_msout_sp);
    cudaGetSymbolAddress((void**)&Wv_sp, g_Wv_sp);
    cudaGetSymbolAddress((void**)&Ws_sp, g_Ws_sp);
    cudaGetSymbolAddress((void**)&Wa_sp, g_Wa_sp);
    cudaGetSymbolAddress((void**)&Wo_sp, g_Wo_sp);

    cudaFuncSetAttribute(gemm_split, cudaFuncAttributeMaxDynamicSharedMemorySize,
                         GEMM_SMEM);

    const dim3 blk(256);
    const int  mTiles = (ROWS + 127) / 128;        // 192
    const int  aBlocks = ROWS * 64 / 256;          // 6120

    // 1) weights -> split fragment layout (tiny)
    convert_W4<<<dim3(64, 4), blk>>>(Wv, Wv_sp, 256, Ws, Ws_sp, 256,
                                     Wa, Wa_sp, 128, Wo, Wo_sp, 256);
    // 2) inpf + query -> split fragment layout
    convert_A2<<<dim3(aBlocks, 2), blk>>>(inpf, inpf_sp, query, query_sp, ROWS);
    // 3) value / offs / alog in ONE launch (y = 2 + 2 + 1 = 5, 128-wide tiles)
    gemm_split<<<dim3(mTiles, 5), blk, GEMM_SMEM>>>(
        inpf_sp,  Wv_sp, bv, value, 256, 2,
        query_sp, Ws_sp, bs, offs,  256, 2,
        query_sp, Wa_sp, ba, alog,  128,
        ROWS);
    // 4) fused softmax + sampling + bf16-split epilogue (writes msout_sp)
    sample_kernel<<<ROWS, blk>>>(value, offs, alog, refp, msout_sp);
    // 5) out = msout @ Wo + bo  (y = 2)
    gemm_split<<<dim3(mTiles, 2), blk, GEMM_SMEM>>>(
        msout_sp, Wo_sp, bo, out, 256, 2,
        msout_sp, Wo_sp, bo, out, 256, 0,
        msout_sp, Wo_sp, bo, out, 256,
        ROWS);
}